// round 3
// baseline (speedup 1.0000x reference)
#include <cuda_runtime.h>
#include <math.h>

#define NN 100000
#define F1 64
#define F2 40
#define NEG_SLOPE 0.2f
#define EPS 1e-16f

// ---- scratch (static __device__ arrays; no allocation allowed) ----
__device__ float g_h1[(size_t)NN * F1];
__device__ float g_acc1[(size_t)NN * F1];
__device__ float g_h2[(size_t)NN * F2];
__device__ float g_acc2[(size_t)NN * F2];
__device__ float g_as[NN];
__device__ float g_ad[NN];
__device__ float g_s[NN];
__device__ int   g_menc[NN];
__device__ int   g_is64;   // 1 if edge_index is int64, 0 if int32

// order-preserving float->int encoding for atomicMax
__device__ __forceinline__ int enc_f(float f) {
    int i = __float_as_int(f);
    return (i >= 0) ? i : (i ^ 0x7FFFFFFF);
}
__device__ __forceinline__ float dec_f(int i) {
    return __int_as_float((i >= 0) ? i : (i ^ 0x7FFFFFFF));
}
#define NEG_INF_ENC ((int)0x807FFFFF)   // enc(-inf)

// ---- detect edge_index dtype: int64 values < 2^31 have all-zero high words ----
__global__ void detect_dtype_kernel(const int* __restrict__ ei32, int nwords) {
    __shared__ int any;
    if (threadIdx.x == 0) any = 0;
    __syncthreads();
    int v = 0;
    // check odd words of the first 4096 logical entries (or as many as exist)
    int limit = 2 * 4096;
    if (limit > nwords) limit = nwords;
    for (int w = 2 * threadIdx.x + 1; w < limit; w += 2 * blockDim.x) v |= ei32[w];
    if (v) atomicOr(&any, 1);
    __syncthreads();
    if (threadIdx.x == 0) g_is64 = (any == 0) ? 1 : 0;
}

__device__ __forceinline__ void edge_endpoints(const void* __restrict__ ei,
                                               int E, int i, int& src, int& dst) {
    if (i >= E) { src = dst = i - E; return; }  // self loop
    if (g_is64) {
        const long long* p = (const long long*)ei;
        src = (int)p[i];
        dst = (int)p[E + i];
    } else {
        const int* p = (const int*)ei;
        src = p[i];
        dst = p[E + i];
    }
}

// ---- h = x @ W, alpha_s = h.a_src, alpha_d = h.a_dst  (one 64-thr block per node)
template <int K, int F, int LAYER>
__global__ void gemm_alpha_kernel(const float* __restrict__ x,
                                  const float* __restrict__ W,
                                  const float* __restrict__ a_src,
                                  const float* __restrict__ a_dst) {
    const float* xin = (LAYER == 1) ? x : g_acc1;
    float* h = (LAYER == 1) ? g_h1 : g_h2;

    __shared__ float xs[K];
    __shared__ float red[64];
    int n = blockIdx.x;
    int t = threadIdx.x;  // blockDim = 64
    if (t < K) xs[t] = xin[(size_t)n * K + t];
    __syncthreads();

    float acc = 0.f;
    if (t < F) {
#pragma unroll
        for (int k = 0; k < K; k++) acc += xs[k] * W[k * F + t];
        h[(size_t)n * F + t] = acc;
    }

    float vs = (t < F) ? acc * a_src[t] : 0.f;
    float vd = (t < F) ? acc * a_dst[t] : 0.f;

    red[t] = vs;
    __syncthreads();
    for (int o = 32; o > 0; o >>= 1) {
        if (t < o) red[t] += red[t + o];
        __syncthreads();
    }
    if (t == 0) g_as[n] = red[0];
    __syncthreads();
    red[t] = vd;
    __syncthreads();
    for (int o = 32; o > 0; o >>= 1) {
        if (t < o) red[t] += red[t + o];
        __syncthreads();
    }
    if (t == 0) g_ad[n] = red[0];
}

// ---- per-layer init: zero acc, reset m/s
template <int LAYER>
__global__ void init_kernel(int total_acc) {
    float* acc = (LAYER == 1) ? g_acc1 : g_acc2;
    int i = blockIdx.x * blockDim.x + threadIdx.x;
    if (i < total_acc) acc[i] = 0.f;
    if (i < NN) {
        g_menc[i] = NEG_INF_ENC;
        g_s[i] = 0.f;
    }
}

// ---- pass A: segment max over dst (thread per edge)
__global__ void edge_max_kernel(const void* __restrict__ ei, int E, int Etot) {
    int i = blockIdx.x * blockDim.x + threadIdx.x;
    if (i >= Etot) return;
    int src, dst;
    edge_endpoints(ei, E, i, src, dst);
    float sc = g_as[src] + g_ad[dst];
    sc = sc > 0.f ? sc : NEG_SLOPE * sc;
    atomicMax(&g_menc[dst], enc_f(sc));
}

// ---- pass B: accumulate s[dst] += w and acc[dst] += w*h[src] (warp per edge)
template <int F, int LAYER>
__global__ void edge_accum_kernel(const void* __restrict__ ei, int E, int Etot) {
    const float* h = (LAYER == 1) ? g_h1 : g_h2;
    float* acc = (LAYER == 1) ? g_acc1 : g_acc2;

    int gw = (blockIdx.x * blockDim.x + threadIdx.x) >> 5;
    int lane = threadIdx.x & 31;
    if (gw >= Etot) return;
    int src, dst;
    edge_endpoints(ei, E, gw, src, dst);
    float sc = g_as[src] + g_ad[dst];
    sc = sc > 0.f ? sc : NEG_SLOPE * sc;
    float w = __expf(sc - dec_f(g_menc[dst]));
    if (lane == 0) atomicAdd(&g_s[dst], w);
    const float* hs = h + (size_t)src * F;
    float* ac = acc + (size_t)dst * F;
#pragma unroll
    for (int f = lane; f < F; f += 32) atomicAdd(&ac[f], w * hs[f]);
}

// ---- finalize layer 1: relu(acc/(s+eps) + b), in place
__global__ void finalize_relu_kernel(const float* __restrict__ b) {
    int i = blockIdx.x * blockDim.x + threadIdx.x;
    if (i >= NN * F1) return;
    int n = i >> 6;          // /F1
    int f = i & (F1 - 1);
    float v = g_acc1[i] / (g_s[n] + EPS) + b[f];
    g_acc1[i] = v > 0.f ? v : 0.f;
}

// ---- finalize layer 2 + log_softmax (warp per node)
__global__ void finalize_logsoftmax_kernel(const float* __restrict__ b,
                                           float* __restrict__ out) {
    int gw = (blockIdx.x * blockDim.x + threadIdx.x) >> 5;
    int lane = threadIdx.x & 31;
    if (gw >= NN) return;
    float inv = 1.f / (g_s[gw] + EPS);
    const float* a = g_acc2 + (size_t)gw * F2;
    float v0 = (lane < F2) ? a[lane] * inv + b[lane] : -INFINITY;
    int l2 = lane + 32;
    float v1 = (l2 < F2) ? a[l2] * inv + b[l2] : -INFINITY;
    float mx = fmaxf(v0, v1);
#pragma unroll
    for (int o = 16; o > 0; o >>= 1) mx = fmaxf(mx, __shfl_xor_sync(0xFFFFFFFFu, mx, o));
    float e = ((lane < F2) ? __expf(v0 - mx) : 0.f) + ((l2 < F2) ? __expf(v1 - mx) : 0.f);
#pragma unroll
    for (int o = 16; o > 0; o >>= 1) e += __shfl_xor_sync(0xFFFFFFFFu, e, o);
    float lse = mx + logf(e);
    float* o_ = out + (size_t)gw * F2;
    if (lane < F2) o_[lane] = v0 - lse;
    if (l2 < F2) o_[l2] = v1 - lse;
}

extern "C" void kernel_launch(void* const* d_in, const int* in_sizes, int n_in,
                              void* d_out, int out_size) {
    const float* x      = (const float*)d_in[0];
    const void*  ei     = d_in[1];
    const float* W1     = (const float*)d_in[2];
    const float* a_src1 = (const float*)d_in[3];
    const float* a_dst1 = (const float*)d_in[4];
    const float* b1     = (const float*)d_in[5];
    const float* W2     = (const float*)d_in[6];
    const float* a_src2 = (const float*)d_in[7];
    const float* a_dst2 = (const float*)d_in[8];
    const float* b2     = (const float*)d_in[9];
    float* out = (float*)d_out;

    int E = in_sizes[1] / 2;   // element count of edge_index / 2
    int Etot = E + NN;

    const int TB = 256;
    int edge_blocks  = (Etot + TB - 1) / TB;
    long long ew = (long long)Etot * 32;
    int ewarp_blocks = (int)((ew + TB - 1) / TB);

    // dtype probe: if int64, odd 32-bit words of small values are all zero.
    // When metadata says int32, nwords = in_sizes[1]; when int64 it would be
    // 2*in_sizes[1] 32-bit words — use in_sizes[1] as a safe lower bound.
    detect_dtype_kernel<<<1, 256>>>((const int*)ei, in_sizes[1]);

    // ===== layer 1 =====
    gemm_alpha_kernel<F1, F1, 1><<<NN, 64>>>(x, W1, a_src1, a_dst1);
    init_kernel<1><<<(NN * F1 + TB - 1) / TB, TB>>>(NN * F1);
    edge_max_kernel<<<edge_blocks, TB>>>(ei, E, Etot);
    edge_accum_kernel<F1, 1><<<ewarp_blocks, TB>>>(ei, E, Etot);
    finalize_relu_kernel<<<(NN * F1 + TB - 1) / TB, TB>>>(b1);

    // ===== layer 2 =====
    gemm_alpha_kernel<F1, F2, 2><<<NN, 64>>>(nullptr, W2, a_src2, a_dst2);
    init_kernel<2><<<(NN * F1 + TB - 1) / TB, TB>>>(NN * F2);
    edge_max_kernel<<<edge_blocks, TB>>>(ei, E, Etot);
    edge_accum_kernel<F2, 2><<<ewarp_blocks, TB>>>(ei, E, Etot);
    finalize_logsoftmax_kernel<<<(NN * 32 + TB - 1) / TB, TB>>>(b2, out);
}

// round 4
// speedup vs baseline: 2.0047x; 2.0047x over previous
#include <cuda_runtime.h>
#include <math.h>

#define NN 100000
#define F1 64
#define F2 40
#define NEG_SLOPE 0.2f
#define EPS 1e-16f
#define EMAX 2200000   // Etot = E + NN = 1.7M actual; headroom

// ---- scratch (static __device__ arrays; no allocation allowed) ----
__device__ float g_h1[(size_t)NN * F1];
__device__ float g_acc1[(size_t)NN * F1];   // relu(layer1 out) = layer2 input
__device__ float g_h2[(size_t)NN * F2];
__device__ float g_as[NN];
__device__ float g_ad[NN];
__device__ int   g_deg[NN];
__device__ int   g_rowptr[NN + 1];
__device__ int   g_cursor[NN];
__device__ int   g_esrc[EMAX];
__device__ int   g_is64;   // 1 if edge_index is int64, 0 if int32

// ---- detect edge_index dtype: int64 values < 2^31 have all-zero high words ----
__global__ void detect_dtype_kernel(const int* __restrict__ ei32, int nwords) {
    __shared__ int any;
    if (threadIdx.x == 0) any = 0;
    __syncthreads();
    int v = 0;
    int limit = 2 * 4096;
    if (limit > nwords) limit = nwords;
    for (int w = 2 * threadIdx.x + 1; w < limit; w += 2 * blockDim.x) v |= ei32[w];
    if (v) atomicOr(&any, 1);
    __syncthreads();
    if (threadIdx.x == 0) g_is64 = (any == 0) ? 1 : 0;
}

__device__ __forceinline__ void edge_endpoints(const void* __restrict__ ei,
                                               int E, int i, int& src, int& dst) {
    if (i >= E) { src = dst = i - E; return; }  // self loop
    if (g_is64) {
        const long long* p = (const long long*)ei;
        src = (int)p[i];
        dst = (int)p[E + i];
    } else {
        const int* p = (const int*)ei;
        src = p[i];
        dst = p[E + i];
    }
}

// ================= CSR build =================
__global__ void init_deg_kernel() {
    int i = blockIdx.x * blockDim.x + threadIdx.x;
    if (i < NN) g_deg[i] = 1;   // self loop
}

__global__ void count_kernel(const void* __restrict__ ei, int E) {
    int i = blockIdx.x * blockDim.x + threadIdx.x;
    if (i >= E) return;
    int src, dst;
    edge_endpoints(ei, E, i, src, dst);
    atomicAdd(&g_deg[dst], 1);
}

// single-block two-level exclusive scan over g_deg -> g_rowptr / g_cursor
__global__ void scan_kernel() {
    __shared__ int part[1024];
    int t = threadIdx.x;
    const int CH = (NN + 1023) / 1024;   // 98
    int start = t * CH;
    int stop = start + CH;
    if (stop > NN) stop = NN;
    int sum = 0;
    for (int i = start; i < stop; i++) sum += g_deg[i];
    part[t] = sum;
    __syncthreads();
    // inclusive scan over partials
    for (int off = 1; off < 1024; off <<= 1) {
        int v = (t >= off) ? part[t - off] : 0;
        __syncthreads();
        part[t] += v;
        __syncthreads();
    }
    int base = (t == 0) ? 0 : part[t - 1];
    for (int i = start; i < stop; i++) {
        g_rowptr[i] = base;
        g_cursor[i] = base;
        base += g_deg[i];
    }
    if (t == 0) g_rowptr[NN] = part[1023];
}

__global__ void scatter_kernel(const void* __restrict__ ei, int E, int Etot) {
    int i = blockIdx.x * blockDim.x + threadIdx.x;
    if (i >= Etot) return;
    int src, dst;
    edge_endpoints(ei, E, i, src, dst);
    int pos = atomicAdd(&g_cursor[dst], 1);
    g_esrc[pos] = src;
}

// ================= per-layer dense part =================
// h = x @ W, as = h.a_src, ad = h.a_dst  (one 64-thr block per node)
template <int K, int F, int LAYER>
__global__ void gemm_alpha_kernel(const float* __restrict__ x,
                                  const float* __restrict__ W,
                                  const float* __restrict__ a_src,
                                  const float* __restrict__ a_dst) {
    const float* xin = (LAYER == 1) ? x : g_acc1;
    float* h = (LAYER == 1) ? g_h1 : g_h2;

    __shared__ float xs[K];
    __shared__ float red[64];
    int n = blockIdx.x;
    int t = threadIdx.x;  // blockDim = 64
    if (t < K) xs[t] = xin[(size_t)n * K + t];
    __syncthreads();

    float acc = 0.f;
    if (t < F) {
#pragma unroll
        for (int k = 0; k < K; k++) acc += xs[k] * W[k * F + t];
        h[(size_t)n * F + t] = acc;
    }

    float vs = (t < F) ? acc * a_src[t] : 0.f;
    float vd = (t < F) ? acc * a_dst[t] : 0.f;

    red[t] = vs;
    __syncthreads();
    for (int o = 32; o > 0; o >>= 1) {
        if (t < o) red[t] += red[t + o];
        __syncthreads();
    }
    if (t == 0) g_as[n] = red[0];
    __syncthreads();
    red[t] = vd;
    __syncthreads();
    for (int o = 32; o > 0; o >>= 1) {
        if (t < o) red[t] += red[t + o];
        __syncthreads();
    }
    if (t == 0) g_ad[n] = red[0];
}

// ================= GAT aggregation: one warp per dst node =================
// Computes segment max, softmax weights, weighted gather-sum, and the layer
// epilogue (relu+b or log_softmax) all in registers. No float atomics.
template <int F, int LAYER>
__global__ void gat_node_kernel(const float* __restrict__ b,
                                float* __restrict__ out) {
    const float* __restrict__ h = (LAYER == 1) ? g_h1 : g_h2;

    __shared__ float sw[8][32];
    __shared__ int   ss[8][32];

    int wslot = threadIdx.x >> 5;
    int lane = threadIdx.x & 31;
    int n = blockIdx.x * 8 + wslot;
    if (n >= NN) return;

    int row = g_rowptr[n];
    int end = g_rowptr[n + 1];
    float adn = g_ad[n];

    // pass 1: segment max over in-edges
    float m = -INFINITY;
    for (int e = row + lane; e < end; e += 32) {
        float sc = g_as[g_esrc[e]] + adn;
        sc = sc > 0.f ? sc : NEG_SLOPE * sc;
        m = fmaxf(m, sc);
    }
#pragma unroll
    for (int o = 16; o > 0; o >>= 1) m = fmaxf(m, __shfl_xor_sync(0xFFFFFFFFu, m, o));

    // pass 2: chunked weight compute + register accumulation
    const bool has2 = (F > 32) && (lane + 32 < F);
    float s_sum = 0.f, a0 = 0.f, a1 = 0.f;
    for (int base = row; base < end; base += 32) {
        int e = base + lane;
        float w = 0.f;
        int src = 0;
        if (e < end) {
            src = g_esrc[e];
            float sc = g_as[src] + adn;
            sc = sc > 0.f ? sc : NEG_SLOPE * sc;
            w = __expf(sc - m);
        }
        s_sum += w;
        sw[wslot][lane] = w;
        ss[wslot][lane] = src;
        __syncwarp();
        int cnt = end - base;
        if (cnt >= 32) {
#pragma unroll 8
            for (int j = 0; j < 32; j++) {
                float wj = sw[wslot][j];
                const float* hs = h + (size_t)ss[wslot][j] * F;
                a0 += wj * hs[lane];
                if (has2) a1 += wj * hs[lane + 32];
            }
        } else {
            for (int j = 0; j < cnt; j++) {
                float wj = sw[wslot][j];
                const float* hs = h + (size_t)ss[wslot][j] * F;
                a0 += wj * hs[lane];
                if (has2) a1 += wj * hs[lane + 32];
            }
        }
        __syncwarp();
    }
#pragma unroll
    for (int o = 16; o > 0; o >>= 1) s_sum += __shfl_xor_sync(0xFFFFFFFFu, s_sum, o);

    float inv = 1.f / (s_sum + EPS);
    if (LAYER == 1) {
        // relu(acc/s + b) -> g_acc1
        float v0 = a0 * inv + b[lane];
        g_acc1[(size_t)n * F + lane] = v0 > 0.f ? v0 : 0.f;
        float v1 = a1 * inv + b[lane + 32];
        g_acc1[(size_t)n * F + lane + 32] = v1 > 0.f ? v1 : 0.f;
    } else {
        // log_softmax over F=40 values held as (v0 on all lanes, v1 on lanes<8)
        float v0 = a0 * inv + b[lane];
        float v1 = has2 ? (a1 * inv + b[lane + 32]) : -INFINITY;
        float mx = fmaxf(v0, v1);
#pragma unroll
        for (int o = 16; o > 0; o >>= 1) mx = fmaxf(mx, __shfl_xor_sync(0xFFFFFFFFu, mx, o));
        float e = __expf(v0 - mx) + (has2 ? __expf(v1 - mx) : 0.f);
#pragma unroll
        for (int o = 16; o > 0; o >>= 1) e += __shfl_xor_sync(0xFFFFFFFFu, e, o);
        float lse = mx + logf(e);
        float* o_ = out + (size_t)n * F;
        o_[lane] = v0 - lse;
        if (has2) o_[lane + 32] = v1 - lse;
    }
}

extern "C" void kernel_launch(void* const* d_in, const int* in_sizes, int n_in,
                              void* d_out, int out_size) {
    const float* x      = (const float*)d_in[0];
    const void*  ei     = d_in[1];
    const float* W1     = (const float*)d_in[2];
    const float* a_src1 = (const float*)d_in[3];
    const float* a_dst1 = (const float*)d_in[4];
    const float* b1     = (const float*)d_in[5];
    const float* W2     = (const float*)d_in[6];
    const float* a_src2 = (const float*)d_in[7];
    const float* a_dst2 = (const float*)d_in[8];
    const float* b2     = (const float*)d_in[9];
    float* out = (float*)d_out;

    int E = in_sizes[1] / 2;
    int Etot = E + NN;

    const int TB = 256;
    int eb  = (E + TB - 1) / TB;
    int etb = (Etot + TB - 1) / TB;
    int nb  = (NN + TB - 1) / TB;
    int gat_blocks = (NN + 7) / 8;

    // ---- CSR build (reused by both layers) ----
    detect_dtype_kernel<<<1, 256>>>((const int*)ei, in_sizes[1]);
    init_deg_kernel<<<nb, TB>>>();
    count_kernel<<<eb, TB>>>(ei, E);
    scan_kernel<<<1, 1024>>>();
    scatter_kernel<<<etb, TB>>>(ei, E, Etot);

    // ---- layer 1 ----
    gemm_alpha_kernel<F1, F1, 1><<<NN, 64>>>(x, W1, a_src1, a_dst1);
    gat_node_kernel<F1, 1><<<gat_blocks, 256>>>(b1, nullptr);

    // ---- layer 2 ----
    gemm_alpha_kernel<F1, F2, 2><<<NN, 64>>>(nullptr, W2, a_src2, a_dst2);
    gat_node_kernel<F2, 2><<<gat_blocks, 256>>>(b2, out);
}

// round 5
// speedup vs baseline: 3.2903x; 1.6413x over previous
#include <cuda_runtime.h>
#include <math.h>

#define NN 100000
#define F1 64
#define F2 40
#define NEG_SLOPE 0.2f
#define EPS 1e-16f
#define EMAX 2200000   // Etot = E + NN = 1.7M actual; headroom
#define NB_SCAN ((NN + 255) / 256)   // 391

// ---- scratch (static __device__ arrays; no allocation allowed) ----
__device__ float g_h1[(size_t)NN * F1];
__device__ float g_acc1[(size_t)NN * F1];   // relu(layer1 out) = layer2 input
__device__ float g_h2[(size_t)NN * F2];
__device__ float g_as[NN];
__device__ float g_ad[NN];
__device__ int   g_deg[NN];
__device__ int   g_rowptr[NN + 1];
__device__ int   g_cursor[NN];
__device__ int   g_esrc[EMAX];
__device__ int   g_part[NB_SCAN];
__device__ int   g_partoff[NB_SCAN];
__device__ int   g_is64;   // 1 if edge_index is int64, 0 if int32

// ---- detect edge_index dtype: int64 values < 2^31 have all-zero high words ----
__global__ void detect_dtype_kernel(const int* __restrict__ ei32, int nwords) {
    __shared__ int any;
    if (threadIdx.x == 0) any = 0;
    __syncthreads();
    int v = 0;
    int limit = 2 * 4096;
    if (limit > nwords) limit = nwords;
    for (int w = 2 * threadIdx.x + 1; w < limit; w += 2 * blockDim.x) v |= ei32[w];
    if (v) atomicOr(&any, 1);
    __syncthreads();
    if (threadIdx.x == 0) g_is64 = (any == 0) ? 1 : 0;
}

__device__ __forceinline__ void edge_endpoints(const void* __restrict__ ei,
                                               int E, int i, int& src, int& dst) {
    if (i >= E) { src = dst = i - E; return; }  // self loop
    if (g_is64) {
        const long long* p = (const long long*)ei;
        src = (int)p[i];
        dst = (int)p[E + i];
    } else {
        const int* p = (const int*)ei;
        src = p[i];
        dst = p[E + i];
    }
}

// ================= CSR build =================
__global__ void init_deg_kernel() {
    int i = blockIdx.x * blockDim.x + threadIdx.x;
    if (i < NN) g_deg[i] = 1;   // self loop
}

__global__ void count_kernel(const void* __restrict__ ei, int E) {
    int i = blockIdx.x * blockDim.x + threadIdx.x;
    if (i >= E) return;
    int src, dst;
    edge_endpoints(ei, E, i, src, dst);
    atomicAdd(&g_deg[dst], 1);
}

// --- scan stage 1: per-block sums of g_deg (256 elems/block) ---
__global__ void block_sum_kernel() {
    __shared__ int red[256];
    int t = threadIdx.x;
    int i = blockIdx.x * 256 + t;
    red[t] = (i < NN) ? g_deg[i] : 0;
    __syncthreads();
    for (int o = 128; o > 0; o >>= 1) {
        if (t < o) red[t] += red[t + o];
        __syncthreads();
    }
    if (t == 0) g_part[blockIdx.x] = red[0];
}

// --- scan stage 2: 1 block scans NB_SCAN partials -> exclusive offsets ---
__global__ void part_scan_kernel() {
    __shared__ int sh[512];
    int t = threadIdx.x;  // 512
    int v = (t < NB_SCAN) ? g_part[t] : 0;
    sh[t] = v;
    __syncthreads();
    for (int o = 1; o < 512; o <<= 1) {
        int u = (t >= o) ? sh[t - o] : 0;
        __syncthreads();
        sh[t] += u;
        __syncthreads();
    }
    if (t < NB_SCAN) g_partoff[t] = sh[t] - v;   // exclusive
    if (t == 511) g_rowptr[NN] = sh[511];        // total
}

// --- scan stage 3: per-block exclusive scan + base -> rowptr/cursor ---
__global__ void rowptr_kernel() {
    __shared__ int sh[256];
    int t = threadIdx.x;
    int i = blockIdx.x * 256 + t;
    int v = (i < NN) ? g_deg[i] : 0;
    sh[t] = v;
    __syncthreads();
    for (int o = 1; o < 256; o <<= 1) {
        int u = (t >= o) ? sh[t - o] : 0;
        __syncthreads();
        sh[t] += u;
        __syncthreads();
    }
    if (i < NN) {
        int r = g_partoff[blockIdx.x] + sh[t] - v;  // exclusive
        g_rowptr[i] = r;
        g_cursor[i] = r;
    }
}

__global__ void scatter_kernel(const void* __restrict__ ei, int E, int Etot) {
    int i = blockIdx.x * blockDim.x + threadIdx.x;
    if (i >= Etot) return;
    int src, dst;
    edge_endpoints(ei, E, i, src, dst);
    int pos = atomicAdd(&g_cursor[dst], 1);
    g_esrc[pos] = src;
}

// ================= per-layer dense part =================
// h = x @ W, as = h.a_src, ad = h.a_dst  (one 64-thr block per node)
template <int K, int F, int LAYER>
__global__ void gemm_alpha_kernel(const float* __restrict__ x,
                                  const float* __restrict__ W,
                                  const float* __restrict__ a_src,
                                  const float* __restrict__ a_dst) {
    const float* xin = (LAYER == 1) ? x : g_acc1;
    float* h = (LAYER == 1) ? g_h1 : g_h2;

    __shared__ float xs[K];
    __shared__ float red2[4];   // [warp][{s,d}]
    int n = blockIdx.x;
    int t = threadIdx.x;  // blockDim = 64
    int wrp = t >> 5, lane = t & 31;
    if (t < K) xs[t] = xin[(size_t)n * K + t];
    __syncthreads();

    float acc = 0.f;
    if (t < F) {
#pragma unroll
        for (int k = 0; k < K; k++) acc += xs[k] * W[k * F + t];
        h[(size_t)n * F + t] = acc;
    }

    float vs = (t < F) ? acc * a_src[t] : 0.f;
    float vd = (t < F) ? acc * a_dst[t] : 0.f;
#pragma unroll
    for (int o = 16; o > 0; o >>= 1) {
        vs += __shfl_xor_sync(0xFFFFFFFFu, vs, o);
        vd += __shfl_xor_sync(0xFFFFFFFFu, vd, o);
    }
    if (lane == 0) { red2[wrp * 2] = vs; red2[wrp * 2 + 1] = vd; }
    __syncthreads();
    if (t == 0) g_as[n] = red2[0] + red2[2];
    if (t == 1) g_ad[n] = red2[1] + red2[3];
}

// ================= GAT aggregation: one warp per dst node =================
// Single-pass online softmax: running max + rescaled accumulators.
// No float atomics, no separate max pass.
template <int F, int LAYER>
__global__ void gat_node_kernel(const float* __restrict__ b,
                                float* __restrict__ out) {
    const float* __restrict__ h = (LAYER == 1) ? g_h1 : g_h2;

    __shared__ float sw[8][32];
    __shared__ int   ss[8][32];

    int wslot = threadIdx.x >> 5;
    int lane = threadIdx.x & 31;
    int n = blockIdx.x * 8 + wslot;
    if (n >= NN) return;

    int row = g_rowptr[n];
    int end = g_rowptr[n + 1];
    float adn = g_ad[n];

    const bool has2 = (F > 32) && (lane + 32 < F);
    float M = -INFINITY, s_sum = 0.f, a0 = 0.f, a1 = 0.f;

    for (int base = row; base < end; base += 32) {
        int e = base + lane;
        float sc = -INFINITY;
        int src = 0;
        if (e < end) {
            src = __ldg(&g_esrc[e]);
            sc = __ldg(&g_as[src]) + adn;
            sc = sc > 0.f ? sc : NEG_SLOPE * sc;
        }
        // chunk max -> new running max
        float cm = sc;
#pragma unroll
        for (int o = 16; o > 0; o >>= 1) cm = fmaxf(cm, __shfl_xor_sync(0xFFFFFFFFu, cm, o));
        float newM = fmaxf(M, cm);
        float scale = __expf(M - newM);   // 0 on first chunk (M=-inf)
        s_sum *= scale; a0 *= scale; a1 *= scale;

        float w = (e < end) ? __expf(sc - newM) : 0.f;
        s_sum += w;
        sw[wslot][lane] = w;
        ss[wslot][lane] = src;
        __syncwarp();
        int cnt = end - base;
        if (cnt > 32) cnt = 32;
        if (cnt == 32) {
#pragma unroll 8
            for (int j = 0; j < 32; j++) {
                float wj = sw[wslot][j];
                const float* hs = h + (size_t)ss[wslot][j] * F;
                a0 += wj * __ldg(&hs[lane]);
                if (has2) a1 += wj * __ldg(&hs[lane + 32]);
            }
        } else {
            for (int j = 0; j < cnt; j++) {
                float wj = sw[wslot][j];
                const float* hs = h + (size_t)ss[wslot][j] * F;
                a0 += wj * __ldg(&hs[lane]);
                if (has2) a1 += wj * __ldg(&hs[lane + 32]);
            }
        }
        __syncwarp();
        M = newM;
    }
#pragma unroll
    for (int o = 16; o > 0; o >>= 1) s_sum += __shfl_xor_sync(0xFFFFFFFFu, s_sum, o);

    float inv = 1.f / (s_sum + EPS);
    if (LAYER == 1) {
        float v0 = a0 * inv + b[lane];
        g_acc1[(size_t)n * F + lane] = v0 > 0.f ? v0 : 0.f;
        float v1 = a1 * inv + b[lane + 32];
        g_acc1[(size_t)n * F + lane + 32] = v1 > 0.f ? v1 : 0.f;
    } else {
        float v0 = a0 * inv + b[lane];
        float v1 = has2 ? (a1 * inv + b[lane + 32]) : -INFINITY;
        float mx = fmaxf(v0, v1);
#pragma unroll
        for (int o = 16; o > 0; o >>= 1) mx = fmaxf(mx, __shfl_xor_sync(0xFFFFFFFFu, mx, o));
        float e = __expf(v0 - mx) + (has2 ? __expf(v1 - mx) : 0.f);
#pragma unroll
        for (int o = 16; o > 0; o >>= 1) e += __shfl_xor_sync(0xFFFFFFFFu, e, o);
        float lse = mx + logf(e);
        float* o_ = out + (size_t)n * F;
        o_[lane] = v0 - lse;
        if (has2) o_[lane + 32] = v1 - lse;
    }
}

extern "C" void kernel_launch(void* const* d_in, const int* in_sizes, int n_in,
                              void* d_out, int out_size) {
    const float* x      = (const float*)d_in[0];
    const void*  ei     = d_in[1];
    const float* W1     = (const float*)d_in[2];
    const float* a_src1 = (const float*)d_in[3];
    const float* a_dst1 = (const float*)d_in[4];
    const float* b1     = (const float*)d_in[5];
    const float* W2     = (const float*)d_in[6];
    const float* a_src2 = (const float*)d_in[7];
    const float* a_dst2 = (const float*)d_in[8];
    const float* b2     = (const float*)d_in[9];
    float* out = (float*)d_out;

    int E = in_sizes[1] / 2;
    int Etot = E + NN;

    const int TB = 256;
    int eb  = (E + TB - 1) / TB;
    int etb = (Etot + TB - 1) / TB;
    int nb  = (NN + TB - 1) / TB;
    int gat_blocks = (NN + 7) / 8;

    // ---- CSR build (reused by both layers) ----
    detect_dtype_kernel<<<1, 256>>>((const int*)ei, in_sizes[1]);
    init_deg_kernel<<<nb, TB>>>();
    count_kernel<<<eb, TB>>>(ei, E);
    block_sum_kernel<<<NB_SCAN, 256>>>();
    part_scan_kernel<<<1, 512>>>();
    rowptr_kernel<<<NB_SCAN, 256>>>();
    scatter_kernel<<<etb, TB>>>(ei, E, Etot);

    // ---- layer 1 ----
    gemm_alpha_kernel<F1, F1, 1><<<NN, 64>>>(x, W1, a_src1, a_dst1);
    gat_node_kernel<F1, 1><<<gat_blocks, 256>>>(b1, nullptr);

    // ---- layer 2 ----
    gemm_alpha_kernel<F1, F2, 2><<<NN, 64>>>(nullptr, W2, a_src2, a_dst2);
    gat_node_kernel<F2, 2><<<gat_blocks, 256>>>(b2, out);
}

// round 7
// speedup vs baseline: 3.4439x; 1.0467x over previous
#include <cuda_runtime.h>
#include <math.h>

#define NN 100000
#define F1 64
#define F2 40
#define NEG_SLOPE 0.2f
#define EPS 1e-16f
#define EMAX 2200000   // Etot = E + NN = 1.7M actual; headroom
#define NB_SCAN ((NN + 255) / 256)   // 391

// ---- scratch (static __device__ arrays; no allocation allowed) ----
__device__ float g_h1[(size_t)NN * F1];
__device__ float g_acc1[(size_t)NN * F1];   // relu(layer1 out) = layer2 input
__device__ float g_h2[(size_t)NN * F2];
__device__ float g_as[NN];
__device__ float g_ad[NN];
__device__ int   g_deg[NN];
__device__ int   g_rowptr[NN + 1];
__device__ int   g_cursor[NN];
__device__ int   g_esrc[EMAX];
__device__ int   g_part[NB_SCAN];
__device__ int   g_partoff[NB_SCAN];
__device__ int   g_is64;   // 1 if edge_index is int64, 0 if int32

// ---- detect edge_index dtype: int64 values < 2^31 have all-zero high words ----
__global__ void detect_dtype_kernel(const int* __restrict__ ei32, int nwords) {
    __shared__ int any;
    if (threadIdx.x == 0) any = 0;
    __syncthreads();
    int v = 0;
    int limit = 2 * 4096;
    if (limit > nwords) limit = nwords;
    for (int w = 2 * threadIdx.x + 1; w < limit; w += 2 * blockDim.x) v |= ei32[w];
    if (v) atomicOr(&any, 1);
    __syncthreads();
    if (threadIdx.x == 0) g_is64 = (any == 0) ? 1 : 0;
}

__device__ __forceinline__ void edge_endpoints(const void* __restrict__ ei,
                                               int E, int i, int& src, int& dst) {
    if (i >= E) { src = dst = i - E; return; }  // self loop
    if (g_is64) {
        const long long* p = (const long long*)ei;
        src = (int)p[i];
        dst = (int)p[E + i];
    } else {
        const int* p = (const int*)ei;
        src = p[i];
        dst = p[E + i];
    }
}

// ================= CSR build =================
__global__ void init_deg_kernel() {
    int i = blockIdx.x * blockDim.x + threadIdx.x;
    if (i < NN) g_deg[i] = 1;   // self loop
}

__global__ void count_kernel(const void* __restrict__ ei, int E) {
    int i = blockIdx.x * blockDim.x + threadIdx.x;
    if (i >= E) return;
    int src, dst;
    edge_endpoints(ei, E, i, src, dst);
    atomicAdd(&g_deg[dst], 1);
}

// --- scan stage 1: per-block sums of g_deg (256 elems/block) ---
__global__ void block_sum_kernel() {
    __shared__ int red[256];
    int t = threadIdx.x;
    int i = blockIdx.x * 256 + t;
    red[t] = (i < NN) ? g_deg[i] : 0;
    __syncthreads();
    for (int o = 128; o > 0; o >>= 1) {
        if (t < o) red[t] += red[t + o];
        __syncthreads();
    }
    if (t == 0) g_part[blockIdx.x] = red[0];
}

// --- scan stage 2: 1 block scans NB_SCAN partials -> exclusive offsets ---
__global__ void part_scan_kernel() {
    __shared__ int sh[512];
    int t = threadIdx.x;  // 512
    int v = (t < NB_SCAN) ? g_part[t] : 0;
    sh[t] = v;
    __syncthreads();
    for (int o = 1; o < 512; o <<= 1) {
        int u = (t >= o) ? sh[t - o] : 0;
        __syncthreads();
        sh[t] += u;
        __syncthreads();
    }
    if (t < NB_SCAN) g_partoff[t] = sh[t] - v;   // exclusive
    if (t == 511) g_rowptr[NN] = sh[511];        // total
}

// --- scan stage 3: per-block exclusive scan + base -> rowptr/cursor ---
__global__ void rowptr_kernel() {
    __shared__ int sh[256];
    int t = threadIdx.x;
    int i = blockIdx.x * 256 + t;
    int v = (i < NN) ? g_deg[i] : 0;
    sh[t] = v;
    __syncthreads();
    for (int o = 1; o < 256; o <<= 1) {
        int u = (t >= o) ? sh[t - o] : 0;
        __syncthreads();
        sh[t] += u;
        __syncthreads();
    }
    if (i < NN) {
        int r = g_partoff[blockIdx.x] + sh[t] - v;  // exclusive
        g_rowptr[i] = r;
        g_cursor[i] = r;
    }
}

__global__ void scatter_kernel(const void* __restrict__ ei, int E, int Etot) {
    int i = blockIdx.x * blockDim.x + threadIdx.x;
    if (i >= Etot) return;
    int src, dst;
    edge_endpoints(ei, E, i, src, dst);
    int pos = atomicAdd(&g_cursor[dst], 1);
    g_esrc[pos] = src;
}

// ================= per-layer dense part =================
// h = x @ W, as = h.a_src, ad = h.a_dst  (one 64-thr block per node)
template <int K, int F, int LAYER>
__global__ void gemm_alpha_kernel(const float* __restrict__ x,
                                  const float* __restrict__ W,
                                  const float* __restrict__ a_src,
                                  const float* __restrict__ a_dst) {
    const float* xin = (LAYER == 1) ? x : g_acc1;
    float* h = (LAYER == 1) ? g_h1 : g_h2;

    __shared__ float xs[K];
    __shared__ float red2[4];   // [warp][{s,d}]
    int n = blockIdx.x;
    int t = threadIdx.x;  // blockDim = 64
    int wrp = t >> 5, lane = t & 31;
    if (t < K) xs[t] = xin[(size_t)n * K + t];
    __syncthreads();

    float acc = 0.f;
    if (t < F) {
#pragma unroll
        for (int k = 0; k < K; k++) acc += xs[k] * W[k * F + t];
        h[(size_t)n * F + t] = acc;
    }

    float vs = (t < F) ? acc * a_src[t] : 0.f;
    float vd = (t < F) ? acc * a_dst[t] : 0.f;
#pragma unroll
    for (int o = 16; o > 0; o >>= 1) {
        vs += __shfl_xor_sync(0xFFFFFFFFu, vs, o);
        vd += __shfl_xor_sync(0xFFFFFFFFu, vd, o);
    }
    if (lane == 0) { red2[wrp * 2] = vs; red2[wrp * 2 + 1] = vd; }
    __syncthreads();
    if (t == 0) g_as[n] = red2[0] + red2[2];
    if (t == 1) g_ad[n] = red2[1] + red2[3];
}

// ================= GAT aggregation: one warp per dst node =================
// Online softmax + edge-parallel float4 gathers with compile-time trip count.
// F=64: 2 edges/step x 16 lanes; F=40: 3 edges/step x 10 lanes.
template <int F, int LAYER>
__global__ void gat_node_kernel(const float* __restrict__ b,
                                float* __restrict__ out) {
    const float* __restrict__ h = (LAYER == 1) ? g_h1 : g_h2;
    constexpr int NF4 = F / 4;          // float4 chunks per row
    constexpr int EPR = 32 / NF4;       // edges per gather step

    __shared__ float sw[8][36];
    __shared__ int   ss[8][36];

    int wslot = threadIdx.x >> 5;
    int lane = threadIdx.x & 31;
    // zero padding entries (indices 32..35) once
    if (lane < 4) { sw[wslot][32 + lane] = 0.f; ss[wslot][32 + lane] = 0; }
    __syncwarp();

    int n = blockIdx.x * 8 + wslot;
    if (n >= NN) return;

    int sub = lane / NF4;               // which edge in a step
    int c   = lane % NF4;               // which float4 chunk
    bool active = sub < EPR;

    int row = g_rowptr[n];
    int end = g_rowptr[n + 1];
    float adn = g_ad[n];

    float M = -INFINITY, s_sum = 0.f;
    float4 acc = make_float4(0.f, 0.f, 0.f, 0.f);

    for (int base = row; base < end; base += 32) {
        int e = base + lane;
        float sc = -INFINITY;
        int src = 0;
        if (e < end) {
            src = __ldg(&g_esrc[e]);
            sc = __ldg(&g_as[src]) + adn;
            sc = sc > 0.f ? sc : NEG_SLOPE * sc;
        }
        // chunk max -> new running max
        float cm = sc;
#pragma unroll
        for (int o = 16; o > 0; o >>= 1) cm = fmaxf(cm, __shfl_xor_sync(0xFFFFFFFFu, cm, o));
        float newM = fmaxf(M, cm);
        float scale = __expf(M - newM);   // 0 on first chunk
        s_sum *= scale;
        acc.x *= scale; acc.y *= scale; acc.z *= scale; acc.w *= scale;

        float w = (e < end) ? __expf(sc - newM) : 0.f;
        s_sum += w;
        sw[wslot][lane] = w;
        ss[wslot][lane] = src;
        __syncwarp();

        // fixed-trip, fully unrolled gather: EPR edges per step, float4 per lane
#pragma unroll
        for (int j2 = 0; j2 < 32; j2 += EPR) {
            int j = j2 + sub;           // j <= 33 -> padded region is zeroed
            float wj = active ? sw[wslot][j] : 0.f;
            const float4* hs = (const float4*)(h + (size_t)ss[wslot][j] * F);
            float4 v = __ldg(&hs[c]);
            acc.x += wj * v.x; acc.y += wj * v.y;
            acc.z += wj * v.z; acc.w += wj * v.w;
        }
        __syncwarp();
        M = newM;
    }
#pragma unroll
    for (int o = 16; o > 0; o >>= 1) s_sum += __shfl_xor_sync(0xFFFFFFFFu, s_sum, o);
    float inv = 1.f / (s_sum + EPS);

    // combine accumulators across subs -> lanes 0..NF4-1 hold chunk c final
    if (EPR == 2) {
        acc.x += __shfl_xor_sync(0xFFFFFFFFu, acc.x, 16);
        acc.y += __shfl_xor_sync(0xFFFFFFFFu, acc.y, 16);
        acc.z += __shfl_xor_sync(0xFFFFFFFFu, acc.z, 16);
        acc.w += __shfl_xor_sync(0xFFFFFFFFu, acc.w, 16);
    } else {
        // EPR == 3: lanes 0..9 += lanes 10..19 and 20..29
        int l1 = lane + NF4, l2 = lane + 2 * NF4;
        float x1 = __shfl_sync(0xFFFFFFFFu, acc.x, l1 & 31), x2 = __shfl_sync(0xFFFFFFFFu, acc.x, l2 & 31);
        float y1 = __shfl_sync(0xFFFFFFFFu, acc.y, l1 & 31), y2 = __shfl_sync(0xFFFFFFFFu, acc.y, l2 & 31);
        float z1 = __shfl_sync(0xFFFFFFFFu, acc.z, l1 & 31), z2 = __shfl_sync(0xFFFFFFFFu, acc.z, l2 & 31);
        float w1 = __shfl_sync(0xFFFFFFFFu, acc.w, l1 & 31), w2 = __shfl_sync(0xFFFFFFFFu, acc.w, l2 & 31);
        acc.x += x1 + x2; acc.y += y1 + y2; acc.z += z1 + z2; acc.w += w1 + w2;
    }

    const float4* b4 = (const float4*)b;
    if (LAYER == 1) {
        if (lane < NF4) {
            float4 bb = b4[c];
            float4 v;
            v.x = fmaxf(acc.x * inv + bb.x, 0.f);
            v.y = fmaxf(acc.y * inv + bb.y, 0.f);
            v.z = fmaxf(acc.z * inv + bb.z, 0.f);
            v.w = fmaxf(acc.w * inv + bb.w, 0.f);
            ((float4*)(g_acc1 + (size_t)n * F))[c] = v;
        }
    } else {
        // log_softmax over F values held as float4 on lanes 0..NF4-1
        float4 v = make_float4(-INFINITY, -INFINITY, -INFINITY, -INFINITY);
        if (lane < NF4) {
            float4 bb = b4[c];
            v.x = acc.x * inv + bb.x;
            v.y = acc.y * inv + bb.y;
            v.z = acc.z * inv + bb.z;
            v.w = acc.w * inv + bb.w;
        }
        float mx = fmaxf(fmaxf(v.x, v.y), fmaxf(v.z, v.w));
#pragma unroll
        for (int o = 16; o > 0; o >>= 1) mx = fmaxf(mx, __shfl_xor_sync(0xFFFFFFFFu, mx, o));
        float es = 0.f;
        if (lane < NF4)
            es = __expf(v.x - mx) + __expf(v.y - mx) + __expf(v.z - mx) + __expf(v.w - mx);
#pragma unroll
        for (int o = 16; o > 0; o >>= 1) es += __shfl_xor_sync(0xFFFFFFFFu, es, o);
        float lse = mx + logf(es);
        if (lane < NF4) {
            float4 r;
            r.x = v.x - lse; r.y = v.y - lse; r.z = v.z - lse; r.w = v.w - lse;
            ((float4*)(out + (size_t)n * F))[c] = r;
        }
    }
}

extern "C" void kernel_launch(void* const* d_in, const int* in_sizes, int n_in,
                              void* d_out, int out_size) {
    const float* x      = (const float*)d_in[0];
    const void*  ei     = d_in[1];
    const float* W1     = (const float*)d_in[2];
    const float* a_src1 = (const float*)d_in[3];
    const float* a_dst1 = (const float*)d_in[4];
    const float* b1     = (const float*)d_in[5];
    const float* W2     = (const float*)d_in[6];
    const float* a_src2 = (const float*)d_in[7];
    const float* a_dst2 = (const float*)d_in[8];
    const float* b2     = (const float*)d_in[9];
    float* out = (float*)d_out;

    int E = in_sizes[1] / 2;
    int Etot = E + NN;

    const int TB = 256;
    int eb  = (E + TB - 1) / TB;
    int etb = (Etot + TB - 1) / TB;
    int nb  = (NN + TB - 1) / TB;
    int gat_blocks = (NN + 7) / 8;

    // ---- CSR build (reused by both layers) ----
    detect_dtype_kernel<<<1, 256>>>((const int*)ei, in_sizes[1]);
    init_deg_kernel<<<nb, TB>>>();
    count_kernel<<<eb, TB>>>(ei, E);
    block_sum_kernel<<<NB_SCAN, 256>>>();
    part_scan_kernel<<<1, 512>>>();
    rowptr_kernel<<<NB_SCAN, 256>>>();
    scatter_kernel<<<etb, TB>>>(ei, E, Etot);

    // ---- layer 1 ----
    gemm_alpha_kernel<F1, F1, 1><<<NN, 64>>>(x, W1, a_src1, a_dst1);
    gat_node_kernel<F1, 1><<<gat_blocks, 256>>>(b1, nullptr);

    // ---- layer 2 ----
    gemm_alpha_kernel<F1, F2, 2><<<NN, 64>>>(nullptr, W2, a_src2, a_dst2);
    gat_node_kernel<F2, 2><<<gat_blocks, 256>>>(b2, out);
}

// round 12
// speedup vs baseline: 3.6073x; 1.0474x over previous
#include <cuda_runtime.h>
#include <math.h>

#define NN 100000
#define F1 64
#define F2 40
#define NEG_SLOPE 0.2f
#define EPS 1e-16f
#define EMAX 2200000   // Etot = E + NN = 1.7M actual; headroom
#define NB_SCAN ((NN + 255) / 256)   // 391

// ---- scratch (static __device__ arrays; no allocation allowed) ----
__device__ float g_h1[(size_t)NN * F1];
__device__ float g_acc1[(size_t)NN * F1];   // relu(layer1 out) = layer2 input
__device__ float g_h2[(size_t)NN * F2];
__device__ float g_as[NN];
__device__ float g_ad[NN];
__device__ int   g_deg[NN];
__device__ int   g_rowptr[NN + 1];
__device__ int   g_cursor[NN];
__device__ int   g_esrc[EMAX];
__device__ int   g_part[NB_SCAN];
__device__ int   g_partoff[NB_SCAN];
__device__ int   g_is64;   // 1 if edge_index is int64, 0 if int32

// ---- detect edge_index dtype: int64 values < 2^31 have all-zero high words ----
__global__ void detect_dtype_kernel(const int* __restrict__ ei32, int nwords) {
    __shared__ int any;
    if (threadIdx.x == 0) any = 0;
    __syncthreads();
    int v = 0;
    int limit = 2 * 4096;
    if (limit > nwords) limit = nwords;
    for (int w = 2 * threadIdx.x + 1; w < limit; w += 2 * blockDim.x) v |= ei32[w];
    if (v) atomicOr(&any, 1);
    __syncthreads();
    if (threadIdx.x == 0) g_is64 = (any == 0) ? 1 : 0;
}

__device__ __forceinline__ void edge_endpoints(const void* __restrict__ ei,
                                               int E, int i, int& src, int& dst) {
    if (i >= E) { src = dst = i - E; return; }  // self loop
    if (g_is64) {
        const long long* p = (const long long*)ei;
        src = (int)p[i];
        dst = (int)p[E + i];
    } else {
        const int* p = (const int*)ei;
        src = p[i];
        dst = p[E + i];
    }
}

// ================= CSR build =================
__global__ void init_deg_kernel() {
    int i = blockIdx.x * blockDim.x + threadIdx.x;
    if (i < NN) g_deg[i] = 1;   // self loop
}

__global__ void count_kernel(const void* __restrict__ ei, int E) {
    int i = blockIdx.x * blockDim.x + threadIdx.x;
    if (i >= E) return;
    int src, dst;
    edge_endpoints(ei, E, i, src, dst);
    atomicAdd(&g_deg[dst], 1);
}

// --- scan stage 1: per-block sums of g_deg (256 elems/block) ---
__global__ void block_sum_kernel() {
    __shared__ int red[256];
    int t = threadIdx.x;
    int i = blockIdx.x * 256 + t;
    red[t] = (i < NN) ? g_deg[i] : 0;
    __syncthreads();
    for (int o = 128; o > 0; o >>= 1) {
        if (t < o) red[t] += red[t + o];
        __syncthreads();
    }
    if (t == 0) g_part[blockIdx.x] = red[0];
}

// --- scan stage 2: 1 block scans NB_SCAN partials -> exclusive offsets ---
__global__ void part_scan_kernel() {
    __shared__ int sh[512];
    int t = threadIdx.x;  // 512
    int v = (t < NB_SCAN) ? g_part[t] : 0;
    sh[t] = v;
    __syncthreads();
    for (int o = 1; o < 512; o <<= 1) {
        int u = (t >= o) ? sh[t - o] : 0;
        __syncthreads();
        sh[t] += u;
        __syncthreads();
    }
    if (t < NB_SCAN) g_partoff[t] = sh[t] - v;   // exclusive
    if (t == 511) g_rowptr[NN] = sh[511];        // total
}

// --- scan stage 3: per-block exclusive scan + base -> rowptr/cursor ---
__global__ void rowptr_kernel() {
    __shared__ int sh[256];
    int t = threadIdx.x;
    int i = blockIdx.x * 256 + t;
    int v = (i < NN) ? g_deg[i] : 0;
    sh[t] = v;
    __syncthreads();
    for (int o = 1; o < 256; o <<= 1) {
        int u = (t >= o) ? sh[t - o] : 0;
        __syncthreads();
        sh[t] += u;
        __syncthreads();
    }
    if (i < NN) {
        int r = g_partoff[blockIdx.x] + sh[t] - v;  // exclusive
        g_rowptr[i] = r;
        g_cursor[i] = r;
    }
}

__global__ void scatter_kernel(const void* __restrict__ ei, int E, int Etot) {
    int i = blockIdx.x * blockDim.x + threadIdx.x;
    if (i >= Etot) return;
    int src, dst;
    edge_endpoints(ei, E, i, src, dst);
    int pos = atomicAdd(&g_cursor[dst], 1);
    g_esrc[pos] = src;
}

// ================= per-layer dense part (tiled) =================
// 256 threads, 32 nodes/block. W + x tile in smem; each thread computes
// FV = F/8 outputs for one node. Alpha dots fold into an 8-lane shuffle.
template <int F, int LAYER>
__global__ void gemm_alpha_tiled(const float* __restrict__ x,
                                 const float* __restrict__ W,
                                 const float* __restrict__ a_src,
                                 const float* __restrict__ a_dst) {
    constexpr int K = 64;
    constexpr int NPB = 32;
    constexpr int FV = F / 8;
    const float* xin = (LAYER == 1) ? x : g_acc1;
    float* h = (LAYER == 1) ? g_h1 : g_h2;

    __shared__ float xs[NPB][K + 1];
    __shared__ __align__(16) float ws[K * F];

    int tid = threadIdx.x;  // 256
    int nbase = blockIdx.x * NPB;

    // load x tile: NPB*K = 2048 floats = 512 float4, 2 per thread
    {
        const float4* xg = (const float4*)(xin + (size_t)nbase * K);
#pragma unroll
        for (int i = 0; i < 2; i++) {
            int idx = tid + i * 256;
            float4 v = __ldg(&xg[idx]);
            int n = idx >> 4;            // / (K/4)
            int kk = (idx & 15) * 4;
            xs[n][kk] = v.x; xs[n][kk + 1] = v.y;
            xs[n][kk + 2] = v.z; xs[n][kk + 3] = v.w;
        }
    }
    // load W: K*F floats as float4
    {
        const float4* wg = (const float4*)W;
        constexpr int NW4 = K * F / 4;
#pragma unroll
        for (int i = 0; i < (NW4 + 255) / 256; i++) {
            int idx = tid + i * 256;
            if (idx < NW4) ((float4*)ws)[idx] = __ldg(&wg[idx]);
        }
    }
    __syncthreads();

    int n_local = tid >> 3;
    int fgroup = tid & 7;
    int fbase = fgroup * FV;

    float acc[FV];
#pragma unroll
    for (int i = 0; i < FV; i++) acc[i] = 0.f;

#pragma unroll 16
    for (int k = 0; k < K; k++) {
        float xv = xs[n_local][k];
#pragma unroll
        for (int i = 0; i < FV; i++) acc[i] += xv * ws[k * F + fbase + i];
    }

    int n = nbase + n_local;
    float* hr = h + (size_t)n * F;
#pragma unroll
    for (int i = 0; i < FV; i++) hr[fbase + i] = acc[i];

    float vs = 0.f, vd = 0.f;
#pragma unroll
    for (int i = 0; i < FV; i++) {
        vs += acc[i] * __ldg(&a_src[fbase + i]);
        vd += acc[i] * __ldg(&a_dst[fbase + i]);
    }
#pragma unroll
    for (int o = 1; o < 8; o <<= 1) {
        vs += __shfl_xor_sync(0xFFFFFFFFu, vs, o);
        vd += __shfl_xor_sync(0xFFFFFFFFu, vd, o);
    }
    if (fgroup == 0) { g_as[n] = vs; g_ad[n] = vd; }
}

// ================= GAT aggregation: one warp per dst node =================
// Online softmax + edge-parallel float4 gathers with compile-time trip count.
// F=64: 2 edges/step x 16 lanes; F=40: 3 edges/step x 10 lanes.
template <int F, int LAYER>
__global__ void gat_node_kernel(const float* __restrict__ b,
                                float* __restrict__ out) {
    const float* __restrict__ h = (LAYER == 1) ? g_h1 : g_h2;
    constexpr int NF4 = F / 4;          // float4 chunks per row
    constexpr int EPR = 32 / NF4;       // edges per gather step

    __shared__ float sw[8][36];
    __shared__ int   ss[8][36];

    int wslot = threadIdx.x >> 5;
    int lane = threadIdx.x & 31;
    if (lane < 4) { sw[wslot][32 + lane] = 0.f; ss[wslot][32 + lane] = 0; }
    __syncwarp();

    int n = blockIdx.x * 8 + wslot;
    if (n >= NN) return;

    int sub = lane / NF4;               // which edge in a step
    int c   = lane % NF4;               // which float4 chunk
    bool active = sub < EPR;

    int row = g_rowptr[n];
    int end = g_rowptr[n + 1];
    float adn = g_ad[n];

    float M = -INFINITY, s_sum = 0.f;
    float4 acc = make_float4(0.f, 0.f, 0.f, 0.f);

    for (int base = row; base < end; base += 32) {
        int e = base + lane;
        float sc = -INFINITY;
        int src = 0;
        if (e < end) {
            src = __ldg(&g_esrc[e]);
            sc = __ldg(&g_as[src]) + adn;
            sc = sc > 0.f ? sc : NEG_SLOPE * sc;
        }
        float cm = sc;
#pragma unroll
        for (int o = 16; o > 0; o >>= 1) cm = fmaxf(cm, __shfl_xor_sync(0xFFFFFFFFu, cm, o));
        float newM = fmaxf(M, cm);
        float scale = __expf(M - newM);
        s_sum *= scale;
        acc.x *= scale; acc.y *= scale; acc.z *= scale; acc.w *= scale;

        float w = (e < end) ? __expf(sc - newM) : 0.f;
        s_sum += w;
        sw[wslot][lane] = w;
        ss[wslot][lane] = src;
        __syncwarp();

#pragma unroll
        for (int j2 = 0; j2 < 32; j2 += EPR) {
            int j = j2 + sub;
            float wj = active ? sw[wslot][j] : 0.f;
            const float4* hs = (const float4*)(h + (size_t)ss[wslot][j] * F);
            float4 v = __ldg(&hs[c]);
            acc.x += wj * v.x; acc.y += wj * v.y;
            acc.z += wj * v.z; acc.w += wj * v.w;
        }
        __syncwarp();
        M = newM;
    }
#pragma unroll
    for (int o = 16; o > 0; o >>= 1) s_sum += __shfl_xor_sync(0xFFFFFFFFu, s_sum, o);
    float inv = 1.f / (s_sum + EPS);

    if (EPR == 2) {
        acc.x += __shfl_xor_sync(0xFFFFFFFFu, acc.x, 16);
        acc.y += __shfl_xor_sync(0xFFFFFFFFu, acc.y, 16);
        acc.z += __shfl_xor_sync(0xFFFFFFFFu, acc.z, 16);
        acc.w += __shfl_xor_sync(0xFFFFFFFFu, acc.w, 16);
    } else {
        int l1 = lane + NF4, l2 = lane + 2 * NF4;
        float x1 = __shfl_sync(0xFFFFFFFFu, acc.x, l1 & 31), x2 = __shfl_sync(0xFFFFFFFFu, acc.x, l2 & 31);
        float y1 = __shfl_sync(0xFFFFFFFFu, acc.y, l1 & 31), y2 = __shfl_sync(0xFFFFFFFFu, acc.y, l2 & 31);
        float z1 = __shfl_sync(0xFFFFFFFFu, acc.z, l1 & 31), z2 = __shfl_sync(0xFFFFFFFFu, acc.z, l2 & 31);
        float w1 = __shfl_sync(0xFFFFFFFFu, acc.w, l1 & 31), w2 = __shfl_sync(0xFFFFFFFFu, acc.w, l2 & 31);
        acc.x += x1 + x2; acc.y += y1 + y2; acc.z += z1 + z2; acc.w += w1 + w2;
    }

    const float4* b4 = (const float4*)b;
    if (LAYER == 1) {
        if (lane < NF4) {
            float4 bb = b4[c];
            float4 v;
            v.x = fmaxf(acc.x * inv + bb.x, 0.f);
            v.y = fmaxf(acc.y * inv + bb.y, 0.f);
            v.z = fmaxf(acc.z * inv + bb.z, 0.f);
            v.w = fmaxf(acc.w * inv + bb.w, 0.f);
            ((float4*)(g_acc1 + (size_t)n * F))[c] = v;
        }
    } else {
        float4 v = make_float4(-INFINITY, -INFINITY, -INFINITY, -INFINITY);
        if (lane < NF4) {
            float4 bb = b4[c];
            v.x = acc.x * inv + bb.x;
            v.y = acc.y * inv + bb.y;
            v.z = acc.z * inv + bb.z;
            v.w = acc.w * inv + bb.w;
        }
        float mx = fmaxf(fmaxf(v.x, v.y), fmaxf(v.z, v.w));
#pragma unroll
        for (int o = 16; o > 0; o >>= 1) mx = fmaxf(mx, __shfl_xor_sync(0xFFFFFFFFu, mx, o));
        float es = 0.f;
        if (lane < NF4)
            es = __expf(v.x - mx) + __expf(v.y - mx) + __expf(v.z - mx) + __expf(v.w - mx);
#pragma unroll
        for (int o = 16; o > 0; o >>= 1) es += __shfl_xor_sync(0xFFFFFFFFu, es, o);
        float lse = mx + logf(es);
        if (lane < NF4) {
            float4 r;
            r.x = v.x - lse; r.y = v.y - lse; r.z = v.z - lse; r.w = v.w - lse;
            ((float4*)(out + (size_t)n * F))[c] = r;
        }
    }
}

extern "C" void kernel_launch(void* const* d_in, const int* in_sizes, int n_in,
                              void* d_out, int out_size) {
    const float* x      = (const float*)d_in[0];
    const void*  ei     = d_in[1];
    const float* W1     = (const float*)d_in[2];
    const float* a_src1 = (const float*)d_in[3];
    const float* a_dst1 = (const float*)d_in[4];
    const float* b1     = (const float*)d_in[5];
    const float* W2     = (const float*)d_in[6];
    const float* a_src2 = (const float*)d_in[7];
    const float* a_dst2 = (const float*)d_in[8];
    const float* b2     = (const float*)d_in[9];
    float* out = (float*)d_out;

    int E = in_sizes[1] / 2;
    int Etot = E + NN;

    const int TB = 256;
    int eb  = (E + TB - 1) / TB;
    int etb = (Etot + TB - 1) / TB;
    int nb  = (NN + TB - 1) / TB;
    int gat_blocks = (NN + 7) / 8;
    int gemm_blocks = NN / 32;   // 3125

    // ---- CSR build (reused by both layers) ----
    detect_dtype_kernel<<<1, 256>>>((const int*)ei, in_sizes[1]);
    init_deg_kernel<<<nb, TB>>>();
    count_kernel<<<eb, TB>>>(ei, E);
    block_sum_kernel<<<NB_SCAN, 256>>>();
    part_scan_kernel<<<1, 512>>>();
    rowptr_kernel<<<NB_SCAN, 256>>>();
    scatter_kernel<<<etb, TB>>>(ei, E, Etot);

    // ---- layer 1 ----
    gemm_alpha_tiled<F1, 1><<<gemm_blocks, 256>>>(x, W1, a_src1, a_dst1);
    gat_node_kernel<F1, 1><<<gat_blocks, 256>>>(b1, nullptr);

    // ---- layer 2 ----
    gemm_alpha_tiled<F2, 2><<<gemm_blocks, 256>>>(nullptr, W2, a_src2, a_dst2);
    gat_node_kernel<F2, 2><<<gat_blocks, 256>>>(b2, out);
}